// round 12
// baseline (speedup 1.0000x reference)
#include <cuda_runtime.h>
#include <math.h>

#define N_NODE 200
#define N_HID  1500
#define N_BAT  20
#define N_IN   6
#define NTH    256          // 8 warps; lanes 0-24 of each warp own one node each

// ---------------- scratch (static device globals; no allocation) ----------------
__device__ float g_wl[N_NODE * N_NODE];
__device__ float g_rowsum[N_NODE];
__device__ float g_part[N_NODE];
__device__ float g_ls[N_NODE * N_NODE];
// transposed noise: [hb = h*20+b][node][2]
__device__ float g_noise[(size_t)N_HID * N_BAT * N_NODE * 2];

// ---------------- prep1: w_l rows + row sums + sq-norm partials ----------------
__global__ void prep1_kernel(const float* __restrict__ sc, const float* __restrict__ wbb) {
    int r = blockIdx.x;
    int c = threadIdx.x;
    float wl = 0.f;
    if (c < N_NODE) {
        float w_rc = expf(wbb[r * N_NODE + c]) * sc[r * N_NODE + c];
        float w_cr = expf(wbb[c * N_NODE + r]) * sc[c * N_NODE + r];
        wl = log1pf(0.5f * (w_rc + w_cr));
        g_wl[r * N_NODE + c] = wl;
    }
    __shared__ float s1[256], s2[256];
    s1[threadIdx.x] = wl;
    s2[threadIdx.x] = wl * wl;
    __syncthreads();
    for (int s = 128; s > 0; s >>= 1) {
        if (threadIdx.x < s) {
            s1[threadIdx.x] += s1[threadIdx.x + s];
            s2[threadIdx.x] += s2[threadIdx.x + s];
        }
        __syncthreads();
    }
    if (threadIdx.x == 0) {
        g_rowsum[r] = s1[0];
        g_part[r]   = s2[0];
    }
}

// ---------------- prep23: per-block redundant norm + build l_s ----------------
__global__ void prep23_kernel() {
    __shared__ float s[256];
    int t = threadIdx.x;
    s[t] = (t < N_NODE) ? g_part[t] : 0.f;
    __syncthreads();
    for (int k = 128; k > 0; k >>= 1) {
        if (t < k) s[t] += s[t + k];
        __syncthreads();
    }
    float invnorm = 1.f / sqrtf(s[0]);   // identical in every block (deterministic)
    int r = blockIdx.x;
    if (t < N_NODE) {
        float v = g_wl[r * N_NODE + t];
        if (t == r) v -= g_rowsum[r];
        g_ls[r * N_NODE + t] = v * invnorm;
    }
}

// ---------------- noise transpose: ext(node,h,b,k) -> g_noise(hb,node,2) ----------
__global__ void transpose_noise_kernel(const float* __restrict__ ext) {
    __shared__ float2 tile[32][33];
    int hb0 = blockIdx.x * 32;
    int n0  = blockIdx.y * 32;
    for (int yy = threadIdx.y; yy < 32; yy += 8) {
        int node = n0 + yy;
        int hb   = hb0 + threadIdx.x;
        float2 v = make_float2(0.f, 0.f);
        if (node < N_NODE && hb < N_HID * N_BAT) {
            const float* s = ext + ((size_t)node * (N_HID * N_BAT) + hb) * N_IN;
            v.x = s[0]; v.y = s[1];
        }
        tile[yy][threadIdx.x] = v;
    }
    __syncthreads();
    for (int yy = threadIdx.y; yy < 32; yy += 8) {
        int hb   = hb0 + yy;
        int node = n0 + threadIdx.x;
        if (node < N_NODE && hb < N_HID * N_BAT) {
            *(float2*)&g_noise[((size_t)hb * N_NODE + node) * 2] = tile[threadIdx.x][yy];
        }
    }
}

// ---------------- simulation helpers ----------------
__device__ __forceinline__ float h_tf_dev(float a, float b, float d, float z) {
    float u   = fmaf(a, z, -b);
    float num = 1e-5f + fabsf(u);
    float den = fmaf(1e-5f, d, fabsf(1.0f - __expf(-d * u)));
    return __fdividef(num, den);
}

__device__ __forceinline__ float tanh_hw(float y) {
    float r;
    asm("tanh.approx.f32 %0, %1;" : "=f"(r) : "f"(y));
    return r;
}

#define FMA2(acc, a, b) \
    asm("fma.rn.f32x2 %0, %1, %2, %0;" : "+l"(acc) : "l"(a), "l"(b))
#define ADD2(acc, a) \
    asm("add.rn.f32x2 %0, %0, %1;" : "+l"(acc) : "l"(a))

__global__ void __launch_bounds__(NTH, 1) sim_kernel(
    const float* __restrict__ ext,   // original layout — only for BOLD n2
    const float* __restrict__ hx,    // (200,6)
    float* __restrict__ out,         // (200,20)
    const float* gp, const float* gEEp, const float* gIEp,
    const float* gEIp, const float* stdp)
{
    // E double buffer: 200 floats each = exactly 50 float4 (16B aligned)
    __shared__ __align__(16) float Ebuf[2][N_NODE];

    const int tid  = threadIdx.x;
    const int w    = tid >> 5;
    const int l    = tid & 31;
    const bool act = (l < 25);
    const int node = w * 25 + (act ? l : 0);   // lanes 25-31 shadow node w*25

    // ---- W: this lane's FULL row, packed as 100 (col2j, col2j+1) f32x2 pairs ----
    unsigned long long W2[100];
#pragma unroll
    for (int j = 0; j < 100; j++) {
        float w0 = act ? g_ls[node * N_NODE + 2 * j]     : 0.f;
        float w1 = act ? g_ls[node * N_NODE + 2 * j + 1] : 0.f;
        asm("mov.b64 %0, {%1, %2};" : "=l"(W2[j]) : "f"(w0), "f"(w1));
    }

    const float gg   = *gp;
    const float cEE  = 0.001f + fmaxf(*gEEp, 0.f);
    const float cIE  = 0.001f + fmaxf(*gIEp, 0.f);
    const float cEI  = 0.001f + fmaxf(*gEIp, 0.f);
    const float nscl = 0.70710678118654752440f * (0.02f + fmaxf(*stdp, 0.f));

    float E = 0.f, I = 0.f, X = 0.f, F = 0.f, V = 0.f, Q = 0.f, vpow = 0.f;

    if (tid < 2 * N_NODE) ((float*)Ebuf)[tid] = 0.f;
    __syncthreads();

    if (act) {
        E = hx[node * 6 + 0];
        I = hx[node * 6 + 1];
        X = hx[node * 6 + 2];
        F = hx[node * 6 + 3];
        V = hx[node * 6 + 4];
        Q = hx[node * 6 + 5];
        vpow = __expf(3.125f * __logf(V));
        Ebuf[0][node] = E;
    }
    __syncthreads();

    float* curE = Ebuf[0];
    float* nxtE = Ebuf[1];

#pragma unroll 1
    for (int b = 0; b < N_BAT; b++) {
        const float* np = g_noise + ((size_t)b * N_NODE + node) * 2;
#pragma unroll 1
        for (int h = 0; h < N_HID; h++) {
            // ---- noise for this step: issued first, covered by the matvec -----
            float nx = 0.f, ny = 0.f;
            if (act) {
                float2 t0 = *(const float2*)np;
                nx = t0.x; ny = t0.y;
            }
            np += (size_t)N_BAT * N_NODE * 2;

            // -------- phase A: full-row dot product, zero reduction ------------
            // 50 broadcast LDS.128 (uniform address -> 1 crossbar phase each)
            unsigned long long a0 = 0ull, a1 = 0ull, a2 = 0ull, a3 = 0ull;
            const ulonglong2* E2 = reinterpret_cast<const ulonglong2*>(curE);
#pragma unroll
            for (int k = 0; k < 25; k++) {
                ulonglong2 e0 = E2[2 * k];
                ulonglong2 e1 = E2[2 * k + 1];
                FMA2(a0, W2[4 * k],     e0.x);
                FMA2(a1, W2[4 * k + 1], e0.y);
                FMA2(a2, W2[4 * k + 2], e1.x);
                FMA2(a3, W2[4 * k + 3], e1.y);
            }
            ADD2(a0, a1);
            ADD2(a2, a3);
            ADD2(a0, a2);
            float plo, phi;
            asm("mov.b64 {%0, %1}, %2;" : "=f"(plo), "=f"(phi) : "l"(a0));
            float dot = plo + phi;

            // -------- phase B: this lane updates its own node ------------------
            if (act) {
                float acc = gg * dot;
                float Eold = E, Iold = I;
                float IE = fmaxf(acc + fmaf(cEE, Eold, 0.32f) - cIE * Iold, 0.f);
                float II = fmaxf(fmaf(cEI, Eold, 0.224f) - Iold, 0.f);
                float rE = h_tf_dev(310.f, 125.f, 0.16f,  IE);
                float rI = h_tf_dev(615.f, 177.f, 0.087f, II);
                float En = Eold + 0.5f * fmaf(0.000641f * (1.f - Eold), rE, -0.01f * Eold)
                                + nscl * nx;
                float In = Iold + 0.5f * fmaf(0.001f, rI, -0.1f * Iold)
                                + nscl * ny;
                E = tanh_hw(1e-5f + fmaxf(En, 0.f));
                I = tanh_hw(1e-5f + fmaxf(In, 0.f));
                nxtE[node] = E;

                // deferred hemodynamics for step h-1 (uses Eold; ILP-overlaps E/I)
                if (h > 0) {
                    X = X + 0.5f * (Eold - X * (1.f / 0.65f) - (F - 1.f) * (1.f / 0.41f));
                    F = F + 0.5f * X;
                    float Vn = fmaf(0.5f / 0.98f, F - vpow, V);
                    float vq = __expf(3.125f * __logf(Vn));
                    float qa = F * (1.f - __expf(__fdividef(-0.41551544396166582194f, F)))
                                 * (1.f / 0.34f);
                    float qb = __fdividef(Q * vq, Vn);
                    Q = fmaf(0.5f / 0.98f, qa - qb, Q);
                    V = Vn; vpow = vq;
                }
            }
            __syncthreads();           // ONE barrier per step: nxtE ready
            float* t2 = curE; curE = nxtE; nxtE = t2;
        }

        // -------- batch end: flush lagging hemo + emit BOLD --------------------
        if (act) {
            float Eold = E;
            X = X + 0.5f * (Eold - X * (1.f / 0.65f) - (F - 1.f) * (1.f / 0.41f));
            F = F + 0.5f * X;
            float Vn = fmaf(0.5f / 0.98f, F - vpow, V);
            float vq = __expf(3.125f * __logf(Vn));
            float qa = F * (1.f - __expf(__fdividef(-0.41551544396166582194f, F)))
                         * (1.f / 0.34f);
            float qb = __fdividef(Q * vq, Vn);
            Q = fmaf(0.5f / 0.98f, qa - qb, Q);
            V = Vn; vpow = vq;

            float n2 = ext[((size_t)(node * N_HID + (N_HID - 1)) * N_BAT + b) * N_IN + 2];
            float bold = 0.02f * n2 +
                5.8823529411764705882f * (2.38f * (1.f - Q)
                                        + 2.f * (1.f - __fdividef(Q, V))
                                        + 0.48f * (1.f - V));
            out[node * N_BAT + b] = bold;
        }
    }
}

// ---------------- launch (exactly 4 kernels) ----------------
extern "C" void kernel_launch(void* const* d_in, const int* in_sizes, int n_in,
                              void* d_out, int out_size) {
    const float* ext  = (const float*)d_in[0];  // external (200,1500,20,6)
    const float* hx   = (const float*)d_in[1];  // hx (200,6)
    // d_in[2] = hE (unused by reference)
    const float* sc   = (const float*)d_in[3];  // sc (200,200)
    const float* wbb  = (const float*)d_in[4];  // w_bb (200,200)
    const float* gp   = (const float*)d_in[5];
    const float* gEE  = (const float*)d_in[6];
    const float* gIE  = (const float*)d_in[7];
    const float* gEI  = (const float*)d_in[8];
    const float* stdp = (const float*)d_in[9];
    float* out = (float*)d_out;

    prep1_kernel<<<N_NODE, 256>>>(sc, wbb);
    prep23_kernel<<<N_NODE, 256>>>();
    {
        dim3 grid((N_HID * N_BAT + 31) / 32, (N_NODE + 31) / 32);
        dim3 blk(32, 8);
        transpose_noise_kernel<<<grid, blk>>>(ext);
    }
    sim_kernel<<<1, NTH>>>(ext, hx, out, gp, gEE, gIE, gEI, stdp);
}